// round 2
// baseline (speedup 1.0000x reference)
#include <cuda_runtime.h>
#include <cstdint>
#include <cstddef>

#define BATCH 128
#define SEQT  1024
#define VD    256
#define NBLK  128
#define TPB   256

// ---------------- device scratch (static, no allocation) ----------------
__device__ float g_h1s[BATCH * SEQT * VD];            // layer-1 hidden states [B,T,V]
__device__ float g_h2s[BATCH * SEQT * VD];            // layer-2 hidden states [B,T,V]
__device__ __align__(128) float g_hbuf[2 * BATCH * VD]; // double-buffered h exchange
__device__ float g_wn[VD * VD];                       // row-normalized fc weight
__device__ unsigned g_bar_cnt = 0;
__device__ unsigned g_bar_gen = 0;

// ---------------- packed f32x2 helpers ----------------
__device__ __forceinline__ float2 fma2(float2 acc, float2 w, float2 v) {
    unsigned long long ua, uw, uv;
    ua = *reinterpret_cast<unsigned long long*>(&acc);
    uw = *reinterpret_cast<unsigned long long*>(&w);
    uv = *reinterpret_cast<unsigned long long*>(&v);
    asm("fma.rn.f32x2 %0, %1, %2, %0;" : "+l"(ua) : "l"(uw), "l"(uv));
    return *reinterpret_cast<float2*>(&ua);
}

__device__ __forceinline__ float2 add2(float2 a, float2 b) {
    unsigned long long ua, ub;
    ua = *reinterpret_cast<unsigned long long*>(&a);
    ub = *reinterpret_cast<unsigned long long*>(&b);
    asm("add.rn.f32x2 %0, %0, %1;" : "+l"(ua) : "l"(ub));
    return *reinterpret_cast<float2*>(&ua);
}

__device__ __forceinline__ float2 shfl_xor2(float2 v, int m) {
    unsigned long long u = *reinterpret_cast<unsigned long long*>(&v);
    u = __shfl_xor_sync(0xffffffffu, u, m);
    return *reinterpret_cast<float2*>(&u);
}

__device__ __forceinline__ float sigmoidf_(float x) {
    return 1.0f / (1.0f + __expf(-x));
}

// accumulate one 4-wide chunk (r fixed) into the 4 gate accumulators
__device__ __forceinline__ void acc_r(float2 acc[4], const float2 W[4][4][4], int r,
                                      float a, float b, float c, float d) {
    float2 a2 = make_float2(a, a);
    float2 b2 = make_float2(b, b);
    float2 c2 = make_float2(c, c);
    float2 d2 = make_float2(d, d);
#pragma unroll
    for (int g = 0; g < 4; ++g) {
        acc[g] = fma2(acc[g], W[g][r][0], a2);
        acc[g] = fma2(acc[g], W[g][r][1], b2);
        acc[g] = fma2(acc[g], W[g][r][2], c2);
        acc[g] = fma2(acc[g], W[g][r][3], d2);
    }
}

// ---------------- persistent fused LSTM layer ----------------
// Grid: 128 blocks (one per pair of hidden columns), 256 threads (8 warps x 16 batch rows).
// Weights for this block's 8 gate rows live in registers. h exchanged via g_hbuf + grid barrier.
__global__ void __launch_bounds__(TPB, 1)
lstm_layer(const float* __restrict__ Xp,
           const float* __restrict__ Wih, const float* __restrict__ Whh,
           const float* __restrict__ bih, const float* __restrict__ bhh,
           int layer) {
    const float* X = layer ? g_h1s : Xp;
    float* HS = layer ? g_h2s : g_h1s;

    const int tid  = threadIdx.x;
    const int warp = tid >> 5;
    const int lane = tid & 31;
    const int v0   = blockIdx.x * 2;

    // --- load this block's 8 weight rows into registers (pair = (v0, v0+1)) ---
    // k ownership of lane l: k = r*128 + l*4 + i, r in [0,4), i in [0,4).
    // r<2 -> W_ih (k in [0,256)), r>=2 -> W_hh (k-256).
    float2 W2[4][4][4];
    float2 bias2[4];
#pragma unroll
    for (int g = 0; g < 4; ++g) {
        const int row0 = g * VD + v0;
        bias2[g] = make_float2(bih[row0] + bhh[row0], bih[row0 + 1] + bhh[row0 + 1]);
#pragma unroll
        for (int r = 0; r < 4; ++r) {
            const float* src = (r < 2) ? Wih : Whh;
            const int kk = (r & 1) * 128 + lane * 4;
#pragma unroll
            for (int i = 0; i < 4; ++i) {
                W2[g][r][i] = make_float2(src[row0 * VD + kk + i],
                                          src[(row0 + 1) * VD + kk + i]);
            }
        }
    }

    const int bl_own = lane >> 1;  // which batch-subindex this lane owns for c/h update
    const int vl     = lane & 1;   // which of the two columns
    float c = 0.0f;

    unsigned gen = g_bar_gen;      // stable at launch (stream-serialized launches)

    for (int t = 0; t < SEQT; ++t) {
        const float* Hread  = g_hbuf + (t & 1) * (BATCH * VD);
        float*       Hwrite = g_hbuf + ((t + 1) & 1) * (BATCH * VD);

#pragma unroll 2
        for (int bl = 0; bl < 16; ++bl) {
            const int b = warp * 16 + bl;
            const float* xb = X + ((size_t)b * SEQT + t) * VD + lane * 4;
            float4 x0 = *(const float4*)(xb);
            float4 x1 = *(const float4*)(xb + 128);
            float4 h0 = make_float4(0.f, 0.f, 0.f, 0.f);
            float4 h1 = h0;
            if (t > 0) {
                const float* hb = Hread + b * VD + lane * 4;
                h0 = *(const float4*)(hb);
                h1 = *(const float4*)(hb + 128);
            }

            float2 acc[4];
#pragma unroll
            for (int g = 0; g < 4; ++g) acc[g] = make_float2(0.f, 0.f);

            acc_r(acc, W2, 0, x0.x, x0.y, x0.z, x0.w);
            acc_r(acc, W2, 1, x1.x, x1.y, x1.z, x1.w);
            acc_r(acc, W2, 2, h0.x, h0.y, h0.z, h0.w);
            acc_r(acc, W2, 3, h1.x, h1.y, h1.z, h1.w);

            // butterfly reduce over 32 lanes (full K=512 dot per gate-pair)
#pragma unroll
            for (int m = 16; m > 0; m >>= 1) {
#pragma unroll
                for (int g = 0; g < 4; ++g)
                    acc[g] = add2(acc[g], shfl_xor2(acc[g], m));
            }

            if (bl_own == bl) {
                const float gi = (vl ? acc[0].y : acc[0].x) + (vl ? bias2[0].y : bias2[0].x);
                const float gf = (vl ? acc[1].y : acc[1].x) + (vl ? bias2[1].y : bias2[1].x);
                const float gg = (vl ? acc[2].y : acc[2].x) + (vl ? bias2[2].y : bias2[2].x);
                const float go = (vl ? acc[3].y : acc[3].x) + (vl ? bias2[3].y : bias2[3].x);
                const float ii = sigmoidf_(gi);
                const float ff = sigmoidf_(gf);
                const float gz = tanhf(gg);
                const float oo = sigmoidf_(go);
                c = ff * c + ii * gz;
                const float hv = oo * tanhf(c);
                Hwrite[b * VD + v0 + vl] = hv;
                HS[((size_t)b * SEQT + t) * VD + v0 + vl] = hv;
            }
        }

        // ---- grid barrier (all 128 co-resident blocks) ----
        __threadfence();
        __syncthreads();
        if (tid == 0) {
            const unsigned target = gen + 1;
            const unsigned arrived = atomicAdd(&g_bar_cnt, 1u);
            if (arrived == NBLK - 1) {
                atomicExch(&g_bar_cnt, 0u);
                __threadfence();
                atomicExch(&g_bar_gen, target);
            } else {
                while (*((volatile unsigned*)&g_bar_gen) != target) { }
            }
            __threadfence();  // reader-side acquire: invalidates L1 before next step's loads
        }
        gen++;
        __syncthreads();
    }
}

// ---------------- fc weight row-normalization ----------------
__global__ void norm_fc(const float* __restrict__ w) {
    const int o = threadIdx.x;
    float s = 0.f;
    for (int v = 0; v < VD; ++v) {
        const float val = w[o * VD + v];
        s += val * val;
    }
    const float inv = 1.0f / sqrtf(s);
    for (int v = 0; v < VD; ++v) g_wn[o * VD + v] = w[o * VD + v] * inv;
}

// ---------------- final FC: out[M,256] = h2s[M,256] @ wn^T + b ----------------
__global__ void __launch_bounds__(256)
fc_kernel(const float* __restrict__ fc_b, float* __restrict__ out) {
    __shared__ float As[16][68];
    __shared__ float Bs[16][68];
    const int tid = threadIdx.x;
    const int bm = blockIdx.x * 64;
    const int bn = blockIdx.y * 64;
    const int tx = tid & 15;
    const int ty = tid >> 4;
    const int lr = tid >> 2;        // tile row (0..63)
    const int lc = (tid & 3) * 4;   // k offset within 16-wide k-tile

    float acc[4][4];
#pragma unroll
    for (int i = 0; i < 4; ++i)
#pragma unroll
        for (int j = 0; j < 4; ++j) acc[i][j] = 0.f;

    for (int k0 = 0; k0 < VD; k0 += 16) {
        float4 a4 = *(const float4*)(g_h2s + ((size_t)(bm + lr)) * VD + k0 + lc);
        float4 b4 = *(const float4*)(g_wn + (bn + lr) * VD + k0 + lc);
        As[lc + 0][lr] = a4.x; As[lc + 1][lr] = a4.y;
        As[lc + 2][lr] = a4.z; As[lc + 3][lr] = a4.w;
        Bs[lc + 0][lr] = b4.x; Bs[lc + 1][lr] = b4.y;
        Bs[lc + 2][lr] = b4.z; Bs[lc + 3][lr] = b4.w;
        __syncthreads();
#pragma unroll
        for (int kk = 0; kk < 16; ++kk) {
            const float4 av = *(const float4*)&As[kk][ty * 4];
            const float4 bv = *(const float4*)&Bs[kk][tx * 4];
            acc[0][0] += av.x * bv.x; acc[0][1] += av.x * bv.y;
            acc[0][2] += av.x * bv.z; acc[0][3] += av.x * bv.w;
            acc[1][0] += av.y * bv.x; acc[1][1] += av.y * bv.y;
            acc[1][2] += av.y * bv.z; acc[1][3] += av.y * bv.w;
            acc[2][0] += av.z * bv.x; acc[2][1] += av.z * bv.y;
            acc[2][2] += av.z * bv.z; acc[2][3] += av.z * bv.w;
            acc[3][0] += av.w * bv.x; acc[3][1] += av.w * bv.y;
            acc[3][2] += av.w * bv.z; acc[3][3] += av.w * bv.w;
        }
        __syncthreads();
    }

#pragma unroll
    for (int i = 0; i < 4; ++i) {
        const size_t row = (size_t)(bm + ty * 4 + i) * VD + bn + tx * 4;
#pragma unroll
        for (int j = 0; j < 4; ++j)
            out[row + j] = acc[i][j] + fc_b[bn + tx * 4 + j];
    }
}

// ---------------- launch ----------------
extern "C" void kernel_launch(void* const* d_in, const int* in_sizes, int n_in,
                              void* d_out, int out_size) {
    (void)in_sizes; (void)n_in; (void)out_size;
    const float* x    = (const float*)d_in[0];
    const float* Wih1 = (const float*)d_in[1];
    const float* Whh1 = (const float*)d_in[2];
    const float* bih1 = (const float*)d_in[3];
    const float* bhh1 = (const float*)d_in[4];
    const float* Wih2 = (const float*)d_in[5];
    const float* Whh2 = (const float*)d_in[6];
    const float* bih2 = (const float*)d_in[7];
    const float* bhh2 = (const float*)d_in[8];
    const float* fcw  = (const float*)d_in[9];
    const float* fcb  = (const float*)d_in[10];
    float* out = (float*)d_out;

    norm_fc<<<1, 256>>>(fcw);
    lstm_layer<<<NBLK, TPB>>>(x, Wih1, Whh1, bih1, bhh1, 0);
    lstm_layer<<<NBLK, TPB>>>(x, Wih2, Whh2, bih2, bhh2, 1);
    dim3 grid(BATCH * SEQT / 64, VD / 64);
    fc_kernel<<<grid, 256>>>(fcb, out);
}

// round 3
// speedup vs baseline: 1.7352x; 1.7352x over previous
#include <cuda_runtime.h>
#include <cstdint>
#include <cstddef>

#define BATCH 128
#define SEQT  1024
#define VD    256
#define NBLK  128
#define TPB   256

// ---------------- device scratch (static, no allocation) ----------------
__device__ float g_xp[134217728];                     // x_proj permuted [T][32][4][128][8] (512MB, reused per layer)
__device__ float g_h1s[BATCH * SEQT * VD];            // layer-1 hidden states [B,T,V]
__device__ float g_h2s[BATCH * SEQT * VD];            // layer-2 hidden states [B,T,V]
__device__ __align__(128) float g_hbuf[2 * BATCH * VD]; // double-buffered h exchange
__device__ float g_wn[VD * VD];                       // row-normalized fc weight
__device__ unsigned g_bar_cnt = 0;
__device__ unsigned g_bar_gen = 0;

// ---------------- packed f32x2 helpers ----------------
__device__ __forceinline__ float2 fma2(float2 acc, float2 w, float2 v) {
    unsigned long long ua, uw, uv;
    ua = *reinterpret_cast<unsigned long long*>(&acc);
    uw = *reinterpret_cast<unsigned long long*>(&w);
    uv = *reinterpret_cast<unsigned long long*>(&v);
    asm("fma.rn.f32x2 %0, %1, %2, %0;" : "+l"(ua) : "l"(uw), "l"(uv));
    return *reinterpret_cast<float2*>(&ua);
}

__device__ __forceinline__ float2 add2(float2 a, float2 b) {
    unsigned long long ua, ub;
    ua = *reinterpret_cast<unsigned long long*>(&a);
    ub = *reinterpret_cast<unsigned long long*>(&b);
    asm("add.rn.f32x2 %0, %0, %1;" : "+l"(ua) : "l"(ub));
    return *reinterpret_cast<float2*>(&ua);
}

__device__ __forceinline__ float2 shfl_xor2(float2 v, int m) {
    unsigned long long u = *reinterpret_cast<unsigned long long*>(&v);
    u = __shfl_xor_sync(0xffffffffu, u, m);
    return *reinterpret_cast<float2*>(&u);
}

__device__ __forceinline__ float sigmoidf_(float x) {
    return 1.0f / (1.0f + __expf(-x));
}

// =======================================================================
// GEMM: x_proj[m][n] = A[m][0:256] . W[n][0:256] + bih[n] + bhh[n]
// A: [M=131072][256] row-major (x or h1s, both flat [b*T+t][V])
// W: [1024][256] row-major
// Output written PERMUTED into g_xp: [t][cgrp(32)][g(4)][b(128)][j(8)]
//   where n = g*256 + cgrp*8 + j
// Tiling: BM=128 (one b, 128 consecutive t), BN=64, BK=16, 256 thr, TM=8 TN=4
// =======================================================================
#define GBK 16

__global__ void __launch_bounds__(256)
gemm_xproj(const float* __restrict__ A, const float* __restrict__ W,
           const float* __restrict__ bih, const float* __restrict__ bhh) {
    __shared__ float As[2][GBK][132];
    __shared__ float Bs[2][GBK][68];

    const int tid = threadIdx.x;
    const int m0 = blockIdx.x * 128;   // gridDim.x = 1024
    const int n0 = blockIdx.y * 64;    // gridDim.y = 16
    const int tm = tid >> 4;           // 0..15
    const int tn = tid & 15;           // 0..15

    const int lr = tid >> 2;           // 0..63
    const int lc = (tid & 3) * 4;      // k offset 0,4,8,12

    const float* Aptr  = A + (size_t)(m0 + lr) * 256 + lc;
    const float* Aptr2 = A + (size_t)(m0 + 64 + lr) * 256 + lc;
    const float* Wptr  = W + (size_t)(n0 + lr) * 256 + lc;

    float2 acc[8][2];
#pragma unroll
    for (int i = 0; i < 8; ++i) { acc[i][0] = make_float2(0.f, 0.f); acc[i][1] = make_float2(0.f, 0.f); }

    float4 la0 = *(const float4*)(Aptr);
    float4 la1 = *(const float4*)(Aptr2);
    float4 lb  = *(const float4*)(Wptr);
#pragma unroll
    for (int i = 0; i < 4; ++i) {
        As[0][lc + i][lr]      = (&la0.x)[i];
        As[0][lc + i][64 + lr] = (&la1.x)[i];
        Bs[0][lc + i][lr]      = (&lb.x)[i];
    }
    __syncthreads();

    for (int kt = 0; kt < 16; ++kt) {
        const int buf = kt & 1;
        if (kt < 15) {
            la0 = *(const float4*)(Aptr  + (kt + 1) * 16);
            la1 = *(const float4*)(Aptr2 + (kt + 1) * 16);
            lb  = *(const float4*)(Wptr  + (kt + 1) * 16);
        }
#pragma unroll
        for (int kk = 0; kk < GBK; ++kk) {
            float4 aF0 = *(const float4*)&As[buf][kk][tm * 8];
            float4 aF1 = *(const float4*)&As[buf][kk][tm * 8 + 4];
            float4 bF  = *(const float4*)&Bs[buf][kk][tn * 4];
            float2 bp0 = make_float2(bF.x, bF.y);
            float2 bp1 = make_float2(bF.z, bF.w);
            float av[8] = {aF0.x, aF0.y, aF0.z, aF0.w, aF1.x, aF1.y, aF1.z, aF1.w};
#pragma unroll
            for (int i = 0; i < 8; ++i) {
                float2 ap = make_float2(av[i], av[i]);
                acc[i][0] = fma2(acc[i][0], ap, bp0);
                acc[i][1] = fma2(acc[i][1], ap, bp1);
            }
        }
        if (kt < 15) {
            const int nb = buf ^ 1;
#pragma unroll
            for (int i = 0; i < 4; ++i) {
                As[nb][lc + i][lr]      = (&la0.x)[i];
                As[nb][lc + i][64 + lr] = (&la1.x)[i];
                Bs[nb][lc + i][lr]      = (&lb.x)[i];
            }
        }
        __syncthreads();
    }

    // epilogue: bias + permuted store (STG.128)
    const int n   = n0 + tn * 4;
    float4 bi4 = *(const float4*)(bih + n);
    float4 bh4 = *(const float4*)(bhh + n);
    float4 bias = make_float4(bi4.x + bh4.x, bi4.y + bh4.y, bi4.z + bh4.z, bi4.w + bh4.w);
    const int g   = n >> 8;
    const int col = n & 255;
    const int cg  = col >> 3;
    const int j0  = col & 7;
    const int bb  = m0 >> 10;
    const int t0  = (m0 & 1023) + tm * 8;
#pragma unroll
    for (int mi = 0; mi < 8; ++mi) {
        float4 o;
        o.x = acc[mi][0].x + bias.x;
        o.y = acc[mi][0].y + bias.y;
        o.z = acc[mi][1].x + bias.z;
        o.w = acc[mi][1].y + bias.w;
        *(float4*)(g_xp + ((((size_t)(t0 + mi) * 32 + cg) * 4 + g) * 128 + bb) * 8 + j0) = o;
    }
}

// =======================================================================
// Recurrence: per step, gates[b][32rows] = h[b][0:256] . Whh_slice + xp
// Grid: 128 blocks = 4 bgrp x 32 cgrp. Block tile: Bt=32 batch, Ct=8 cols
// (32 gate rows). 256 threads / 8 warps.
// Warp (wh=warp&3, bhalf=warp>>2): rows wh*8+q (q=lane>>2), k-slice kq=lane&3
// (64 k each). Weights: 64 floats/lane in regs. 2-round butterfly over kq.
// Cell phase: thread (b_loc=tid>>3, j=tid&7) owns c-state in register.
// =======================================================================
__global__ void __launch_bounds__(TPB, 1)
lstm_rec(const float* __restrict__ Whh, int layer) {
    float* HS = layer ? g_h2s : g_h1s;

    const int tid  = threadIdx.x;
    const int lane = tid & 31;
    const int warp = tid >> 5;
    const int cgrp = blockIdx.x & 31;
    const int bgrp = blockIdx.x >> 5;

    const int wh    = warp & 3;
    const int bhalf = warp >> 2;
    const int q     = lane >> 2;
    const int kq    = lane & 3;
    const int rr    = wh * 8 + q;        // 0..31 (= g*8 + j)
    const int gg    = rr >> 3;
    const int jj    = rr & 7;
    const int Rrow  = gg * VD + cgrp * 8 + jj;

    // weights: 64 floats per lane, k-packed float2
    float2 Wr[32];
    const float4* wsrc = (const float4*)(Whh + (size_t)Rrow * VD + kq * 64);
#pragma unroll
    for (int i = 0; i < 16; ++i) {
        float4 w4 = wsrc[i];
        Wr[2 * i]     = make_float2(w4.x, w4.y);
        Wr[2 * i + 1] = make_float2(w4.z, w4.w);
    }

    const int b_loc  = tid >> 3;
    const int j_c    = tid & 7;
    const int b_glob = bgrp * 32 + b_loc;
    float cstate = 0.f;

    __shared__ float4 h_sm4[32 * 64];     // [b][64 float4] = 32KB
    __shared__ float  gates_sm[32][33];

    unsigned gen = g_bar_gen;   // stable at launch

    for (int t = 0; t < SEQT; ++t) {
        // prefetch x_proj for this step's cell phase (independent of barrier)
        float xg[4];
#pragma unroll
        for (int g = 0; g < 4; ++g)
            xg[g] = __ldcs(g_xp + ((((size_t)t * 32 + cgrp) * 4 + g) * 128 + b_glob) * 8 + j_c);

        // stage h into smem (L2-only loads: other SMs wrote it last step)
        if (t == 0) {
            float4 z = make_float4(0.f, 0.f, 0.f, 0.f);
#pragma unroll
            for (int i = 0; i < 8; ++i) h_sm4[i * 256 + tid] = z;
        } else {
            const float4* src = (const float4*)(g_hbuf + (size_t)(t & 1) * (BATCH * VD)) + bgrp * 2048;
#pragma unroll
            for (int i = 0; i < 8; ++i) h_sm4[i * 256 + tid] = __ldcg(src + i * 256 + tid);
        }
        __syncthreads();

        // compute: 16 b per warp, rotated LDS to stay conflict-free
#pragma unroll 2
        for (int bi = 0; bi < 16; ++bi) {
            const int b = bhalf * 16 + bi;
            const float4* hrow = h_sm4 + b * 64 + kq * 16;
            float2 acc = make_float2(0.f, 0.f);
#pragma unroll
            for (int c8 = 0; c8 < 16; ++c8) {
                const int ch = (c8 + kq) & 15;
                float4 hv = hrow[ch];
                acc = fma2(acc, Wr[2 * ch],     make_float2(hv.x, hv.y));
                acc = fma2(acc, Wr[2 * ch + 1], make_float2(hv.z, hv.w));
            }
            acc = add2(acc, shfl_xor2(acc, 1));
            acc = add2(acc, shfl_xor2(acc, 2));
            if (kq == 0) gates_sm[b][rr] = acc.x + acc.y;
        }
        __syncthreads();

        // cell update: thread owns (b_loc, j_c), c-state in register
        {
            const float gi = gates_sm[b_loc][j_c]      + xg[0];
            const float gf = gates_sm[b_loc][8 + j_c]  + xg[1];
            const float gc = gates_sm[b_loc][16 + j_c] + xg[2];
            const float go = gates_sm[b_loc][24 + j_c] + xg[3];
            const float i_ = sigmoidf_(gi);
            const float f_ = sigmoidf_(gf);
            const float z_ = tanhf(gc);
            const float o_ = sigmoidf_(go);
            cstate = f_ * cstate + i_ * z_;
            const float hv = o_ * tanhf(cstate);
            const int col = cgrp * 8 + j_c;
            g_hbuf[(size_t)((t + 1) & 1) * (BATCH * VD) + b_glob * VD + col] = hv;
            HS[((size_t)b_glob * SEQT + t) * VD + col] = hv;
        }

        // grid barrier (128 co-resident blocks)
        __threadfence();
        __syncthreads();
        if (tid == 0) {
            const unsigned target = gen + 1;
            const unsigned arrived = atomicAdd(&g_bar_cnt, 1u);
            if (arrived == NBLK - 1) {
                atomicExch(&g_bar_cnt, 0u);
                __threadfence();
                atomicExch(&g_bar_gen, target);
            } else {
                while (*((volatile unsigned*)&g_bar_gen) != target) { }
            }
        }
        gen++;
        __syncthreads();
    }
}

// ---------------- fc weight row-normalization ----------------
__global__ void norm_fc(const float* __restrict__ w) {
    const int o = threadIdx.x;
    float s = 0.f;
    for (int v = 0; v < VD; ++v) {
        const float val = w[o * VD + v];
        s += val * val;
    }
    const float inv = 1.0f / sqrtf(s);
    for (int v = 0; v < VD; ++v) g_wn[o * VD + v] = w[o * VD + v] * inv;
}

// ---------------- final FC: out[M,256] = h2s[M,256] @ wn^T + b ----------------
__global__ void __launch_bounds__(256)
fc_kernel(const float* __restrict__ fc_b, float* __restrict__ out) {
    __shared__ float As[16][68];
    __shared__ float Bs[16][68];
    const int tid = threadIdx.x;
    const int bm = blockIdx.x * 64;
    const int bn = blockIdx.y * 64;
    const int tx = tid & 15;
    const int ty = tid >> 4;
    const int lr = tid >> 2;
    const int lc = (tid & 3) * 4;

    float acc[4][4];
#pragma unroll
    for (int i = 0; i < 4; ++i)
#pragma unroll
        for (int j = 0; j < 4; ++j) acc[i][j] = 0.f;

    for (int k0 = 0; k0 < VD; k0 += 16) {
        float4 a4 = *(const float4*)(g_h2s + ((size_t)(bm + lr)) * VD + k0 + lc);
        float4 b4 = *(const float4*)(g_wn + (bn + lr) * VD + k0 + lc);
        As[lc + 0][lr] = a4.x; As[lc + 1][lr] = a4.y;
        As[lc + 2][lr] = a4.z; As[lc + 3][lr] = a4.w;
        Bs[lc + 0][lr] = b4.x; Bs[lc + 1][lr] = b4.y;
        Bs[lc + 2][lr] = b4.z; Bs[lc + 3][lr] = b4.w;
        __syncthreads();
#pragma unroll
        for (int kk = 0; kk < 16; ++kk) {
            const float4 av = *(const float4*)&As[kk][ty * 4];
            const float4 bv = *(const float4*)&Bs[kk][tx * 4];
            acc[0][0] += av.x * bv.x; acc[0][1] += av.x * bv.y;
            acc[0][2] += av.x * bv.z; acc[0][3] += av.x * bv.w;
            acc[1][0] += av.y * bv.x; acc[1][1] += av.y * bv.y;
            acc[1][2] += av.y * bv.z; acc[1][3] += av.y * bv.w;
            acc[2][0] += av.z * bv.x; acc[2][1] += av.z * bv.y;
            acc[2][2] += av.z * bv.z; acc[2][3] += av.z * bv.w;
            acc[3][0] += av.w * bv.x; acc[3][1] += av.w * bv.y;
            acc[3][2] += av.w * bv.z; acc[3][3] += av.w * bv.w;
        }
        __syncthreads();
    }

#pragma unroll
    for (int i = 0; i < 4; ++i) {
        const size_t row = (size_t)(bm + ty * 4 + i) * VD + bn + tx * 4;
#pragma unroll
        for (int j = 0; j < 4; ++j)
            out[row + j] = acc[i][j] + fc_b[bn + tx * 4 + j];
    }
}

// ---------------- launch ----------------
extern "C" void kernel_launch(void* const* d_in, const int* in_sizes, int n_in,
                              void* d_out, int out_size) {
    (void)in_sizes; (void)n_in; (void)out_size;
    const float* x    = (const float*)d_in[0];
    const float* Wih1 = (const float*)d_in[1];
    const float* Whh1 = (const float*)d_in[2];
    const float* bih1 = (const float*)d_in[3];
    const float* bhh1 = (const float*)d_in[4];
    const float* Wih2 = (const float*)d_in[5];
    const float* Whh2 = (const float*)d_in[6];
    const float* bih2 = (const float*)d_in[7];
    const float* bhh2 = (const float*)d_in[8];
    const float* fcw  = (const float*)d_in[9];
    const float* fcb  = (const float*)d_in[10];
    float* out = (float*)d_out;

    // resolve device-symbol address of g_h1s for use as GEMM2 input
    float* h1s_ptr = nullptr;
    cudaGetSymbolAddress((void**)&h1s_ptr, g_h1s);

    norm_fc<<<1, 256>>>(fcw);
    dim3 ggrid(1024, 16);
    gemm_xproj<<<ggrid, 256>>>(x, Wih1, bih1, bhh1);
    lstm_rec<<<NBLK, TPB>>>(Whh1, 0);
    gemm_xproj<<<ggrid, 256>>>(h1s_ptr, Wih2, bih2, bhh2);
    lstm_rec<<<NBLK, TPB>>>(Whh2, 1);
    dim3 fgrid(BATCH * SEQT / 64, VD / 64);
    fc_kernel<<<fgrid, 256>>>(fcb, out);
}